// round 15
// baseline (speedup 1.0000x reference)
#include <cuda_runtime.h>
#include <cuda_bf16.h>
#include <math.h>

#define LSEQ 512
#define DM   192
#define DI   384
#define NS   16
#define RK   12
#define XO   44      // RK + 2*NS
#define NLAY 24
#define NCH  32
#define CS   16      // LSEQ / NCH
#define GRID 148
#define NTHR 512

// ---------------- scratch (static device globals; no runtime allocation) ----------------
__device__ float g_hidden[LSEQ * DM];
__device__ float g_resid[2][LSEQ * DM];          // ping-pong
__device__ float g_xz[LSEQ * 2 * DI];
__device__ float g_u[2][LSEQ * DI];
__device__ float g_dtv[2][LSEQ * DI];
__device__ float g_rex[2][LSEQ * DI];
__device__ float g_z[2][LSEQ * DI];
__device__ float g_Bm[2][LSEQ * NS];
__device__ float g_Cm[2][LSEQ * NS];
__device__ float g_PA[2][NCH * NS * DI];
__device__ float g_HE[2][NCH * NS * DI];
__device__ float g_H0[2][NCH * NS * DI];         // prefix state entering each chunk
// patch-embed scratch
__device__ float g_ppart[8 * LSEQ * DM];
// preprocessed weights
__device__ float g_inT[NLAY * DM * 2 * DI];      // [l][k][o]
__device__ float g_outT[NLAY * DI * DM];         // [l][d][c]
__device__ float g_xpT2[NLAY * 2 * XO * DI];     // [l][dir][o][d]
__device__ float g_dtT[2][NLAY * RK * DI];       // [l][r][d]
__device__ float g_base[2][NLAY * DI];           // A0 = -exp(Alog[...,0])
__device__ float g_delta[2][NLAY * NS * DI];     // An - (n+1)*A0, [l][n][d]
__device__ float g_Dva[2][NLAY * DI];
// software grid barrier state (separate cache lines; reset each replay)
__device__ unsigned g_cnt[32];
__device__ volatile unsigned g_epoch[32];

// ---------------- software grid barrier (grid must be exactly GRID blocks) ----------------
__device__ __forceinline__ void gbar(unsigned e) {
    __syncthreads();
    if (threadIdx.x == 0) {
        __threadfence();
        unsigned prev = atomicAdd(&g_cnt[0], 1u);
        if (prev == e * GRID - 1u) {
            g_epoch[0] = e;
            __threadfence();
        } else {
            while (g_epoch[0] < e) __nanosleep(64);
        }
    }
    __syncthreads();
}

// ---------------- launch 0: coalesced tiled transposes of in_w / out_w ----------------
__global__ void k_setup_w(const float* __restrict__ in_w, const float* __restrict__ out_w) {
    __shared__ float tile[32][33];
    int b = blockIdx.x;
    int tx = threadIdx.x & 31, ty = threadIdx.x >> 5;  // 8 rows per pass
    if (b < 3456) {
        // in_w (24, 768, 192) -> g_inT [l][k][o]
        int l = b / 144; int r = b % 144; int ot = r / 6; int kt = r % 6;
        const float* src = in_w + (size_t)l * 768 * 192;
        float* dst = g_inT + (size_t)l * 192 * 768;
        int o0 = ot * 32, k0 = kt * 32;
        for (int rr = ty; rr < 32; rr += 8)
            tile[rr][tx] = src[(size_t)(o0 + rr) * 192 + k0 + tx];
        __syncthreads();
        for (int rr = ty; rr < 32; rr += 8)
            dst[(size_t)(k0 + rr) * 768 + o0 + tx] = tile[tx][rr];
    } else {
        // out_w (24, 192, 384) -> g_outT [l][d][c]
        b -= 3456;
        int l = b / 72; int r = b % 72; int ct = r / 12; int dt = r % 12;
        const float* src = out_w + (size_t)l * 192 * 384;
        float* dst = g_outT + (size_t)l * 384 * 192;
        int c0 = ct * 32, d0 = dt * 32;
        for (int rr = ty; rr < 32; rr += 8)
            tile[rr][tx] = src[(size_t)(c0 + rr) * 384 + d0 + tx];
        __syncthreads();
        for (int rr = ty; rr < 32; rr += 8)
            dst[(size_t)(d0 + rr) * 192 + c0 + tx] = tile[tx][rr];
    }
}

// ---------------- launch 1: small copies + A-derived + zero resid + barrier reset ----------------
__global__ void k_setup_misc(const float* __restrict__ xpf, const float* __restrict__ xpb,
                             const float* __restrict__ dtfw, const float* __restrict__ dtbw,
                             const float* __restrict__ Alog_f, const float* __restrict__ Alog_b,
                             const float* __restrict__ D_f, const float* __restrict__ D_b) {
    int tid = blockIdx.x * blockDim.x + threadIdx.x;
    int nth = gridDim.x * blockDim.x;
    if (tid == 0) { g_cnt[0] = 0; g_epoch[0] = 0; }
    // xp (24,44,384) is already [l][o][d] -> interleave dirs
    for (int i = tid; i < NLAY * XO * DI; i += nth) {
        int l = i / (XO * DI); int r = i % (XO * DI);
        g_xpT2[(size_t)(l * 2 + 0) * XO * DI + r] = xpf[i];
        g_xpT2[(size_t)(l * 2 + 1) * XO * DI + r] = xpb[i];
    }
    // dt_w (24,384,12) -> [l][r][d]
    for (int i = tid; i < NLAY * DI * RK; i += nth) {
        int l = i / (DI * RK); int r2 = i % (DI * RK); int d = r2 / RK; int rr = r2 % RK;
        g_dtT[0][(l * RK + rr) * DI + d] = dtfw[i];
        g_dtT[1][(l * RK + rr) * DI + d] = dtbw[i];
    }
    // A-derived per (l,d)
    for (int i = tid; i < NLAY * DI; i += nth) {
        int l = i / DI; int d = i % DI;
        for (int dir = 0; dir < 2; dir++) {
            const float* Alog = dir ? Alog_b : Alog_f;
            float A0 = -expf(Alog[i * NS + 0]);
            g_base[dir][i] = A0;
            for (int n = 0; n < NS; n++) {
                float An = -expf(Alog[i * NS + n]);
                g_delta[dir][(l * NS + n) * DI + d] = An - (float)(n + 1) * A0;
            }
        }
        g_Dva[0][i] = D_f[i];
        g_Dva[1][i] = D_b[i];
    }
    for (int i = tid; i < LSEQ * DM; i += nth) g_resid[0][i] = 0.f;
}

// ---------------- launch 2: patch embed split-K GEMM with inline gather ----------------
__global__ void k_patch_gemm(const float* __restrict__ x, const float* __restrict__ pw) {
    __shared__ float sA[64][65];
    __shared__ float sB[64][65];
    int p0 = blockIdx.x * 64;
    int c0 = blockIdx.y * 64;
    int ks = blockIdx.z;
    int tid = threadIdx.x;
    int tr = tid >> 4, tc = tid & 15;
    float acc[4][4] = {};
    for (int kt = 0; kt < 8; kt++) {
        int kb = ks * 512 + kt * 64;
        int kk = tid & 63;
        int r0 = tid >> 6;
        for (int r = r0; r < 64; r += 4) {
            int p = p0 + r;
            int k = kb + kk;
            int pz = p >> 6, py = (p >> 3) & 7, px = p & 7;
            int dz = k >> 8, dy = (k >> 4) & 15, dx = k & 15;
            sA[r][kk] = x[((pz * 16 + dz) * 128 + (py * 16 + dy)) * 128 + (px * 16 + dx)];
            sB[kk][r] = pw[(size_t)(c0 + r) * 4096 + kb + kk];
        }
        __syncthreads();
        for (int q = 0; q < 64; q++) {
            float a[4], b[4];
#pragma unroll
            for (int i = 0; i < 4; i++) a[i] = sA[tr * 4 + i][q];
#pragma unroll
            for (int j = 0; j < 4; j++) b[j] = sB[q][tc * 4 + j];
#pragma unroll
            for (int i = 0; i < 4; i++)
#pragma unroll
                for (int j = 0; j < 4; j++)
                    acc[i][j] = fmaf(a[i], b[j], acc[i][j]);
        }
        __syncthreads();
    }
#pragma unroll
    for (int i = 0; i < 4; i++)
#pragma unroll
        for (int j = 0; j < 4; j++)
            g_ppart[((size_t)ks * LSEQ + p0 + tr * 4 + i) * DM + c0 + tc * 4 + j] = acc[i][j];
}

// ---------------- launch 3: THE persistent kernel ----------------
// grid exactly 148 x 512 threads. Cross-block activation reads use __ldcg (L2-only);
// weights written in earlier launches are safe to cache in L1.
__global__ void __launch_bounds__(NTHR) k_mamba(
    const float* __restrict__ ln_w, const float* __restrict__ ln_b,
    const float* __restrict__ cfw, const float* __restrict__ cfb,
    const float* __restrict__ cbw, const float* __restrict__ cbb,
    const float* __restrict__ dtbf, const float* __restrict__ dtbb,
    const float* __restrict__ nfw, const float* __restrict__ nfb,
    const float* __restrict__ hw, const float* __restrict__ hb,
    const float* __restrict__ pb, float* __restrict__ out)
{
    __shared__ float sm[4416];
    const int bid = blockIdx.x;
    const int tid = threadIdx.x;
    unsigned ep = 0;

    // ---- patch reduce (+bias) -> g_hidden ----
    for (int i = bid * NTHR + tid; i < LSEQ * DM; i += GRID * NTHR) {
        int c = i % DM;
        float s = pb[c];
#pragma unroll
        for (int ks = 0; ks < 8; ks++) s += g_ppart[(size_t)ks * LSEQ * DM + i];
        g_hidden[i] = s;
    }
    gbar(++ep);

    for (int l = 0; l < NLAY; l++) {
        // ===== phase IN: residual + LN + inproj GEMM (128 vb of 16 tok x 192 out) =====
        {
            float* shn  = sm;            // 3072
            float* sr1  = sm + 3072;     // 512
            float* sr2  = sm + 3584;     // 512
            float* stat = sm + 4096;     // 32
            int rb = l & 1;
            const float* rsrc = g_resid[rb];
            float* rdst = g_resid[rb ^ 1];
            for (int vb = bid; vb < 128; vb += GRID) {
                int tg = vb & 31, og = vb >> 5;
                int t0 = tg * 16;
                for (int i = tid; i < 16 * DM; i += NTHR) {
                    int tt = i / DM, c = i % DM;
                    float r = __ldcg(&rsrc[(t0 + tt) * DM + c]) + __ldcg(&g_hidden[(t0 + tt) * DM + c]);
                    shn[i] = r;
                    if (og == 0) rdst[(t0 + tt) * DM + c] = r;
                }
                __syncthreads();
                {
                    int tt = tid >> 5, seg = tid & 31;  // 16 tokens x 32 segs of 6
                    float s = 0.f, s2 = 0.f;
#pragma unroll
                    for (int j = 0; j < 6; j++) {
                        float v = shn[tt * DM + seg * 6 + j];
                        s += v; s2 += v * v;
                    }
                    sr1[tt * 32 + seg] = s; sr2[tt * 32 + seg] = s2;
                }
                __syncthreads();
                if (tid < 16) {
                    float s = 0.f, s2 = 0.f;
#pragma unroll
                    for (int j = 0; j < 32; j++) { s += sr1[tid * 32 + j]; s2 += sr2[tid * 32 + j]; }
                    float m = s / DM;
                    stat[tid * 2] = m;
                    stat[tid * 2 + 1] = rsqrtf(s2 / DM - m * m + 1e-5f);
                }
                __syncthreads();
                for (int i = tid; i < 16 * DM; i += NTHR) {
                    int tt = i / DM, c = i % DM;
                    shn[i] = (shn[i] - stat[tt * 2]) * stat[tt * 2 + 1] * ln_w[l * DM + c] + ln_b[l * DM + c];
                }
                __syncthreads();
                int o64 = tid & 63;
                int grp = tid >> 6;  // 8 groups x 2 tokens
                const float* wbase = g_inT + (size_t)(l * DM) * 768 + og * 192 + o64;
                float a0[2] = {}, a1[2] = {}, a2[2] = {};
                for (int k = 0; k < DM; k++) {
                    const float* wk = wbase + (size_t)k * 768;
                    float w0 = wk[0], w1 = wk[64], w2 = wk[128];
#pragma unroll
                    for (int i2 = 0; i2 < 2; i2++) {
                        float xv = shn[(grp * 2 + i2) * DM + k];
                        a0[i2] = fmaf(xv, w0, a0[i2]);
                        a1[i2] = fmaf(xv, w1, a1[i2]);
                        a2[i2] = fmaf(xv, w2, a2[i2]);
                    }
                }
#pragma unroll
                for (int i2 = 0; i2 < 2; i2++) {
                    int t = t0 + grp * 2 + i2;
                    int ob = og * 192 + o64;
                    g_xz[t * 768 + ob] = a0[i2];
                    g_xz[t * 768 + ob + 64] = a1[i2];
                    g_xz[t * 768 + ob + 128] = a2[i2];
                }
                __syncthreads();
            }
        }
        gbar(++ep);

        // ===== phase CONV: conv+silu+xproj+dtproj+rexp (256 vb of dir x 4 scan tokens) =====
        {
            float* sxz  = sm;            // 7*384 = 2688
            float* su   = sm + 2688;     // 1536
            float* sdbl = sm + 4224;     // 176
            for (int vb = bid; vb < 256; vb += GRID) {
                int dir = vb >> 7;
                int q = vb & 127;
                int tq0 = q * 4;
                const float* cw  = dir ? cbw : cfw;
                const float* cb  = dir ? cbb : cfb;
                const float* dtb = dir ? dtbb : dtbf;
                // stage 7 tap rows (scan order)
                for (int i = tid; i < 7 * DI; i += NTHR) {
                    int j = i / DI, d = i % DI;
                    int ts = tq0 - 3 + j;
                    float v = 0.f;
                    if (ts >= 0) {
                        int o = dir ? (511 - ts) : ts;
                        v = __ldcg(&g_xz[o * 768 + d]);
                    }
                    sxz[i] = v;
                }
                __syncthreads();
                // conv + silu; store u (smem+gmem) and z
                for (int e = tid; e < 4 * DI; e += NTHR) {
                    int t = e / DI, d = e % DI;
                    float4 w4 = *reinterpret_cast<const float4*>(&cw[(l * DI + d) * 4]);
                    float acc = cb[l * DI + d];
                    acc = fmaf(sxz[(t + 0) * DI + d], w4.x, acc);
                    acc = fmaf(sxz[(t + 1) * DI + d], w4.y, acc);
                    acc = fmaf(sxz[(t + 2) * DI + d], w4.z, acc);
                    acc = fmaf(sxz[(t + 3) * DI + d], w4.w, acc);
                    float u = acc / (1.f + __expf(-acc));
                    su[e] = u;
                    int tg = tq0 + t;
                    g_u[dir][tg * DI + d] = u;
                    int orig = dir ? (511 - tg) : tg;
                    g_z[dir][tg * DI + d] = __ldcg(&g_xz[orig * 768 + DI + d]);
                }
                __syncthreads();
                // xproj: 4 tokens x 44 outs, 2 threads per dot (192 each), shfl reduce
                if (tid < 352) {
                    int dot = tid >> 1, hf = tid & 1;
                    int t = dot / XO, o = dot % XO;
                    const float4* xp = reinterpret_cast<const float4*>(
                        g_xpT2 + ((size_t)(l * 2 + dir) * XO + o) * DI + hf * 192);
                    const float4* sur = reinterpret_cast<const float4*>(&su[t * DI + hf * 192]);
                    float b0 = 0.f, b1 = 0.f, b2 = 0.f, b3 = 0.f;
#pragma unroll 4
                    for (int qq = 0; qq < 48; qq++) {
                        float4 uu = sur[qq];
                        float4 ww = xp[qq];
                        b0 = fmaf(uu.x, ww.x, b0);
                        b1 = fmaf(uu.y, ww.y, b1);
                        b2 = fmaf(uu.z, ww.z, b2);
                        b3 = fmaf(uu.w, ww.w, b3);
                    }
                    float acc = (b0 + b1) + (b2 + b3);
                    acc += __shfl_xor_sync(0xffffffffu, acc, 1);
                    if (hf == 0) {
                        sdbl[t * XO + o] = acc;
                        int tg = tq0 + t;
                        if (o >= RK + NS)      g_Cm[dir][tg * NS + (o - RK - NS)] = acc;
                        else if (o >= RK)      g_Bm[dir][tg * NS + (o - RK)] = acc;
                    }
                }
                __syncthreads();
                // dtproj + softplus + rexp
                for (int e = tid; e < 4 * DI; e += NTHR) {
                    int t = e / DI, d = e % DI;
                    float a = dtb[l * DI + d];
                    const float* dw = g_dtT[dir] + (size_t)(l * RK) * DI + d;
#pragma unroll
                    for (int r = 0; r < RK; r++)
                        a = fmaf(sdbl[t * XO + r], dw[(size_t)r * DI], a);
                    float dt = (a > 15.f) ? a : log1pf(__expf(a));
                    int tg = tq0 + t;
                    g_dtv[dir][tg * DI + d] = dt;
                    g_rex[dir][tg * DI + d] = __expf(dt * g_base[dir][l * DI + d]);
                }
                __syncthreads();
            }
        }
        gbar(++ep);

        // ===== phase LOCAL: chunk-local scan -> carries (64 vb of dir x chunk) =====
        {
            float* sB = sm;  // 256
            for (int vb = bid; vb < 64; vb += GRID) {
                int dir = vb >> 5;
                int c = vb & 31;
                if (tid < 256) sB[tid] = __ldcg(&g_Bm[dir][c * CS * NS + tid]);
                __syncthreads();
                if (tid < DI) {
                    int d = tid;
                    float delta[NS], h[NS], pa[NS];
#pragma unroll
                    for (int n = 0; n < NS; n++) {
                        delta[n] = g_delta[dir][(l * NS + n) * DI + d];
                        h[n] = 0.f; pa[n] = 1.f;
                    }
                    for (int t = 0; t < CS; t++) {
                        int tg = c * CS + t;
                        float u  = __ldcg(&g_u[dir][tg * DI + d]);
                        float r  = __ldcg(&g_rex[dir][tg * DI + d]);
                        float dt = __ldcg(&g_dtv[dir][tg * DI + d]);
                        float du = dt * u;
                        float p = 1.f;
#pragma unroll
                        for (int n = 0; n < NS; n++) {
                            p *= r;
                            float dA = p * fmaf(dt, delta[n], 1.f);
                            pa[n] *= dA;
                            h[n] = fmaf(dA, h[n], du * sB[t * NS + n]);
                        }
                    }
#pragma unroll
                    for (int n = 0; n < NS; n++) {
                        g_PA[dir][(c * NS + n) * DI + d] = pa[n];
                        g_HE[dir][(c * NS + n) * DI + d] = h[n];
                    }
                }
                __syncthreads();
            }
        }
        gbar(++ep);

        // ===== phase SCAN2: cross-chunk scan of carries -> H0 prefix per chunk =====
        // 12288 independent scans: (dir, n, d), d fastest for coalescing.
        {
            int gt = bid * NTHR + tid;
            if (gt < 2 * NS * DI) {
                int dir = gt / (NS * DI);
                int nd = gt % (NS * DI);   // n*DI + d
                float h = 0.f;
#pragma unroll 4
                for (int c = 0; c < NCH; c++) {
                    size_t idx = (size_t)c * NS * DI + nd;
                    float pa = __ldcg(&g_PA[dir][idx]);
                    float he = __ldcg(&g_HE[dir][idx]);
                    g_H0[dir][idx] = h;
                    h = fmaf(pa, h, he);
                }
            }
        }
        gbar(++ep);

        // ===== phase APPLY+OUT: H0-init + apply + gate + outproj (64 vb of 8 tokens) =====
        // vb g covers orig tokens [8g, 8g+8): dir0 chunk g>>1, dir1 chunk 31-(g>>1).
        {
            float* sy = sm;          // 8*384 = 3072
            float* sB = sm + 3072;   // 256
            float* sC = sm + 3328;   // 256
            for (int vb = bid; vb < 64; vb += GRID) {
                int g = vb;
                int T0 = g * 8;
                for (int dir = 0; dir < 2; dir++) {
                    int cc = dir ? (31 - (g >> 1)) : (g >> 1);
                    if (tid < 256) {
                        sB[tid] = __ldcg(&g_Bm[dir][cc * CS * NS + tid]);
                        sC[tid] = __ldcg(&g_Cm[dir][cc * CS * NS + tid]);
                    }
                    __syncthreads();
                    if (tid < DI) {
                        int d = tid;
                        float delta[NS], h[NS];
#pragma unroll
                        for (int n = 0; n < NS; n++) {
                            delta[n] = g_delta[dir][(l * NS + n) * DI + d];
                            h[n] = __ldcg(&g_H0[dir][(cc * NS + n) * DI + d]);
                        }
                        float Dv = g_Dva[dir][l * DI + d];
                        for (int i = 0; i < CS; i++) {
                            int tg = cc * CS + i;
                            float u  = __ldcg(&g_u[dir][tg * DI + d]);
                            float r  = __ldcg(&g_rex[dir][tg * DI + d]);
                            float dt = __ldcg(&g_dtv[dir][tg * DI + d]);
                            float du = dt * u;
                            float p = 1.f, y = 0.f;
#pragma unroll
                            for (int n = 0; n < NS; n++) {
                                p *= r;
                                float dA = p * fmaf(dt, delta[n], 1.f);
                                h[n] = fmaf(dA, h[n], du * sB[i * NS + n]);
                                y = fmaf(h[n], sC[i * NS + n], y);
                            }
                            int local = dir ? (511 - tg - T0) : (tg - T0);
                            if ((unsigned)local < 8u) {
                                float z = __ldcg(&g_z[dir][tg * DI + d]);
                                y = fmaf(u, Dv, y);
                                float sg = z / (1.f + __expf(-z));
                                float val = y * sg;
                                if (dir == 0) sy[local * DI + d] = val;
                                else          sy[local * DI + d] += val;
                            }
                        }
                    }
                    __syncthreads();
                }
                // outproj: 8 tokens x 192 outs from smem y
                if (tid < 384) {
                    int o = tid % DM;
                    int th = tid / DM;  // 0..1, 4 tokens each
                    const float* wb = g_outT + (size_t)l * DI * DM + o;
                    float acc[4] = {};
#pragma unroll 2
                    for (int k = 0; k < DI; k++) {
                        float w = wb[(size_t)k * DM];
#pragma unroll
                        for (int tt = 0; tt < 4; tt++)
                            acc[tt] = fmaf(sy[(th * 4 + tt) * DI + k], w, acc[tt]);
                    }
#pragma unroll
                    for (int tt = 0; tt < 4; tt++)
                        g_hidden[(T0 + th * 4 + tt) * DM + o] = acc[tt];
                }
                __syncthreads();
            }
        }
        gbar(++ep);
    }

    // ===== final: LN(resid + hidden)[511] @ head (block 0) =====
    if (bid == 0) {
        float* sv   = sm;        // 192
        float* red1 = sm + 192;  // 32
        float* red2 = sm + 224;  // 32
        float* st   = sm + 256;  // 2
        if (tid < DM)
            sv[tid] = __ldcg(&g_resid[0][511 * DM + tid]) + __ldcg(&g_hidden[511 * DM + tid]);
        __syncthreads();
        if (tid < 32) {
            float s = 0.f, s2 = 0.f;
#pragma unroll
            for (int j = 0; j < 6; j++) {
                float x = sv[tid * 6 + j];
                s += x; s2 += x * x;
            }
            red1[tid] = s; red2[tid] = s2;
        }
        __syncthreads();
        if (tid == 0) {
            float s = 0.f, s2 = 0.f;
#pragma unroll
            for (int j = 0; j < 32; j++) { s += red1[j]; s2 += red2[j]; }
            float m = s / DM;
            st[0] = m;
            st[1] = rsqrtf(s2 / DM - m * m + 1e-5f);
        }
        __syncthreads();
        if (tid < DM) sv[tid] = (sv[tid] - st[0]) * st[1] * nfw[tid] + nfb[tid];
        __syncthreads();
        if (tid < 2) {
            float a = hb[tid];
            for (int c = 0; c < DM; c++) a = fmaf(sv[c], hw[tid * DM + c], a);
            out[tid] = a;
        }
    }
}

extern "C" void kernel_launch(void* const* d_in, const int* in_sizes, int n_in,
                              void* d_out, int out_size) {
    const float* x       = (const float*)d_in[0];
    const float* patch_w = (const float*)d_in[1];
    const float* patch_b = (const float*)d_in[2];
    const float* ln_w    = (const float*)d_in[3];
    const float* ln_b    = (const float*)d_in[4];
    const float* in_w    = (const float*)d_in[5];
    const float* cf_w    = (const float*)d_in[6];
    const float* cf_b    = (const float*)d_in[7];
    const float* xpf_w   = (const float*)d_in[8];
    const float* dtf_w   = (const float*)d_in[9];
    const float* dtf_b   = (const float*)d_in[10];
    const float* Alog_f  = (const float*)d_in[11];
    const float* D_f     = (const float*)d_in[12];
    const float* cbk_w   = (const float*)d_in[13];
    const float* cbk_b   = (const float*)d_in[14];
    const float* xpb_w   = (const float*)d_in[15];
    const float* dtb_w   = (const float*)d_in[16];
    const float* dtb_b   = (const float*)d_in[17];
    const float* Alog_b  = (const float*)d_in[18];
    const float* D_b     = (const float*)d_in[19];
    const float* out_w   = (const float*)d_in[20];
    const float* nf_w    = (const float*)d_in[21];
    const float* nf_b    = (const float*)d_in[22];
    const float* head_w  = (const float*)d_in[23];
    const float* head_b  = (const float*)d_in[24];
    float* out = (float*)d_out;

    k_setup_w<<<5184, 256>>>(in_w, out_w);                                   // launch 0
    k_setup_misc<<<256, 256>>>(xpf_w, xpb_w, dtf_w, dtb_w,
                               Alog_f, Alog_b, D_f, D_b);                    // launch 1
    k_patch_gemm<<<dim3(8, 3, 8), 256>>>(x, patch_w);                        // launch 2
    k_mamba<<<GRID, NTHR>>>(ln_w, ln_b, cf_w, cf_b, cbk_w, cbk_b,
                            dtf_b, dtb_b, nf_w, nf_b,
                            head_w, head_b, patch_b, out);                   // launch 3
}

// round 16
// speedup vs baseline: 1.8395x; 1.8395x over previous
#include <cuda_runtime.h>
#include <cuda_bf16.h>
#include <math.h>

#define LSEQ 512
#define DM   192
#define DI   384
#define NS   16
#define RK   12
#define XO   44      // RK + 2*NS
#define NLAY 24
#define NCH  32
#define CS   16      // LSEQ / NCH
#define GRID 148
#define NTHR 512

// ---------------- scratch (static device globals; no runtime allocation) ----------------
__device__ float g_hidden[LSEQ * DM];
__device__ float g_resid[2][LSEQ * DM];          // ping-pong
__device__ float g_xz[LSEQ * 2 * DI];
__device__ float g_u[2][LSEQ * DI];
__device__ float g_dtv[2][LSEQ * DI];
__device__ float g_rex[2][LSEQ * DI];
__device__ float g_Bm[2][LSEQ * NS];
__device__ float g_Cm[2][LSEQ * NS];
__device__ float g_PA[2][NCH * NS * DI];
__device__ float g_HE[2][NCH * NS * DI];
// patch-embed scratch
__device__ float g_ppart[8 * LSEQ * DM];
// preprocessed weights
__device__ float g_inT[NLAY * DM * 2 * DI];      // [l][k][o]
__device__ float g_outT[NLAY * DI * DM];         // [l][d][c]
__device__ float g_xpT2[NLAY * 2 * XO * DI];     // [l][dir][o][d]
__device__ float g_dtT[2][NLAY * RK * DI];       // [l][r][d]
__device__ float g_base[2][NLAY * DI];           // A0 = -exp(Alog[...,0])
__device__ float g_delta[2][NLAY * NS * DI];     // An - (n+1)*A0, [l][n][d]
__device__ float g_Dva[2][NLAY * DI];
// software grid barrier state (separate cache lines; reset each replay)
__device__ unsigned g_cnt[32];
__device__ volatile unsigned g_epoch[32];

// ---------------- software grid barrier (grid must be exactly GRID blocks) ----------------
__device__ __forceinline__ void gbar(unsigned e) {
    __syncthreads();
    if (threadIdx.x == 0) {
        __threadfence();
        unsigned prev = atomicAdd(&g_cnt[0], 1u);
        if (prev == e * GRID - 1u) {
            g_epoch[0] = e;
            __threadfence();
        } else {
            while (g_epoch[0] < e) __nanosleep(64);
        }
    }
    __syncthreads();
}

// ---------------- launch 0: coalesced tiled transposes of in_w / out_w ----------------
__global__ void k_setup_w(const float* __restrict__ in_w, const float* __restrict__ out_w) {
    __shared__ float tile[32][33];
    int b = blockIdx.x;
    int tx = threadIdx.x & 31, ty = threadIdx.x >> 5;  // 8 rows per pass
    if (b < 3456) {
        // in_w (24, 768, 192) -> g_inT [l][k][o]
        int l = b / 144; int r = b % 144; int ot = r / 6; int kt = r % 6;
        const float* src = in_w + (size_t)l * 768 * 192;
        float* dst = g_inT + (size_t)l * 192 * 768;
        int o0 = ot * 32, k0 = kt * 32;
        for (int rr = ty; rr < 32; rr += 8)
            tile[rr][tx] = src[(size_t)(o0 + rr) * 192 + k0 + tx];
        __syncthreads();
        for (int rr = ty; rr < 32; rr += 8)
            dst[(size_t)(k0 + rr) * 768 + o0 + tx] = tile[tx][rr];
    } else {
        // out_w (24, 192, 384) -> g_outT [l][d][c]
        b -= 3456;
        int l = b / 72; int r = b % 72; int ct = r / 12; int dt = r % 12;
        const float* src = out_w + (size_t)l * 192 * 384;
        float* dst = g_outT + (size_t)l * 384 * 192;
        int c0 = ct * 32, d0 = dt * 32;
        for (int rr = ty; rr < 32; rr += 8)
            tile[rr][tx] = src[(size_t)(c0 + rr) * 384 + d0 + tx];
        __syncthreads();
        for (int rr = ty; rr < 32; rr += 8)
            dst[(size_t)(d0 + rr) * 192 + c0 + tx] = tile[tx][rr];
    }
}

// ---------------- launch 1: small copies + A-derived + zero resid + barrier reset ----------------
__global__ void k_setup_misc(const float* __restrict__ xpf, const float* __restrict__ xpb,
                             const float* __restrict__ dtfw, const float* __restrict__ dtbw,
                             const float* __restrict__ Alog_f, const float* __restrict__ Alog_b,
                             const float* __restrict__ D_f, const float* __restrict__ D_b) {
    int tid = blockIdx.x * blockDim.x + threadIdx.x;
    int nth = gridDim.x * blockDim.x;
    if (tid == 0) { g_cnt[0] = 0; g_epoch[0] = 0; }
    // xp (24,44,384) is already [l][o][d] -> interleave dirs
    for (int i = tid; i < NLAY * XO * DI; i += nth) {
        int l = i / (XO * DI); int r = i % (XO * DI);
        g_xpT2[(size_t)(l * 2 + 0) * XO * DI + r] = xpf[i];
        g_xpT2[(size_t)(l * 2 + 1) * XO * DI + r] = xpb[i];
    }
    // dt_w (24,384,12) -> [l][r][d]
    for (int i = tid; i < NLAY * DI * RK; i += nth) {
        int l = i / (DI * RK); int r2 = i % (DI * RK); int d = r2 / RK; int rr = r2 % RK;
        g_dtT[0][(l * RK + rr) * DI + d] = dtfw[i];
        g_dtT[1][(l * RK + rr) * DI + d] = dtbw[i];
    }
    // A-derived per (l,d)
    for (int i = tid; i < NLAY * DI; i += nth) {
        int l = i / DI; int d = i % DI;
        for (int dir = 0; dir < 2; dir++) {
            const float* Alog = dir ? Alog_b : Alog_f;
            float A0 = -expf(Alog[i * NS + 0]);
            g_base[dir][i] = A0;
            for (int n = 0; n < NS; n++) {
                float An = -expf(Alog[i * NS + n]);
                g_delta[dir][(l * NS + n) * DI + d] = An - (float)(n + 1) * A0;
            }
        }
        g_Dva[0][i] = D_f[i];
        g_Dva[1][i] = D_b[i];
    }
    for (int i = tid; i < LSEQ * DM; i += nth) g_resid[0][i] = 0.f;
}

// ---------------- launch 2: patch embed split-K GEMM with inline gather ----------------
__global__ void k_patch_gemm(const float* __restrict__ x, const float* __restrict__ pw) {
    __shared__ float sA[64][65];
    __shared__ float sB[64][65];
    int p0 = blockIdx.x * 64;
    int c0 = blockIdx.y * 64;
    int ks = blockIdx.z;
    int tid = threadIdx.x;
    int tr = tid >> 4, tc = tid & 15;
    float acc[4][4] = {};
    for (int kt = 0; kt < 8; kt++) {
        int kb = ks * 512 + kt * 64;
        int kk = tid & 63;
        int r0 = tid >> 6;
        for (int r = r0; r < 64; r += 4) {
            int p = p0 + r;
            int k = kb + kk;
            int pz = p >> 6, py = (p >> 3) & 7, px = p & 7;
            int dz = k >> 8, dy = (k >> 4) & 15, dx = k & 15;
            sA[r][kk] = x[((pz * 16 + dz) * 128 + (py * 16 + dy)) * 128 + (px * 16 + dx)];
            sB[kk][r] = pw[(size_t)(c0 + r) * 4096 + kb + kk];
        }
        __syncthreads();
        for (int q = 0; q < 64; q++) {
            float a[4], b[4];
#pragma unroll
            for (int i = 0; i < 4; i++) a[i] = sA[tr * 4 + i][q];
#pragma unroll
            for (int j = 0; j < 4; j++) b[j] = sB[q][tc * 4 + j];
#pragma unroll
            for (int i = 0; i < 4; i++)
#pragma unroll
                for (int j = 0; j < 4; j++)
                    acc[i][j] = fmaf(a[i], b[j], acc[i][j]);
        }
        __syncthreads();
    }
#pragma unroll
    for (int i = 0; i < 4; i++)
#pragma unroll
        for (int j = 0; j < 4; j++)
            g_ppart[((size_t)ks * LSEQ + p0 + tr * 4 + i) * DM + c0 + tc * 4 + j] = acc[i][j];
}

// ---------------- launch 3: THE persistent kernel ----------------
// grid exactly 148 x 512 threads. Cross-block activation reads use __ldcg (L2-only);
// weights written in earlier launches are safe to cache in L1.
__global__ void __launch_bounds__(NTHR) k_mamba(
    const float* __restrict__ ln_w, const float* __restrict__ ln_b,
    const float* __restrict__ cfw, const float* __restrict__ cfb,
    const float* __restrict__ cbw, const float* __restrict__ cbb,
    const float* __restrict__ dtbf, const float* __restrict__ dtbb,
    const float* __restrict__ nfw, const float* __restrict__ nfb,
    const float* __restrict__ hw, const float* __restrict__ hb,
    const float* __restrict__ pb, float* __restrict__ out)
{
    __shared__ float sm[4416];
    const int bid = blockIdx.x;
    const int tid = threadIdx.x;
    unsigned ep = 0;

    // ---- patch reduce (+bias) -> g_hidden ----
    for (int i = bid * NTHR + tid; i < LSEQ * DM; i += GRID * NTHR) {
        int c = i % DM;
        float s = pb[c];
#pragma unroll
        for (int ks = 0; ks < 8; ks++) s += g_ppart[(size_t)ks * LSEQ * DM + i];
        g_hidden[i] = s;
    }
    gbar(++ep);

    for (int l = 0; l < NLAY; l++) {
        // ===== phase IN: residual + LN + inproj GEMM (128 vb of 16 tok x 192 out) =====
        {
            float* shn  = sm;            // 3072
            float* sr1  = sm + 3072;     // 512
            float* sr2  = sm + 3584;     // 512
            float* stat = sm + 4096;     // 32
            int rb = l & 1;
            const float* rsrc = g_resid[rb];
            float* rdst = g_resid[rb ^ 1];
            for (int vb = bid; vb < 128; vb += GRID) {
                int tg = vb & 31, og = vb >> 5;
                int t0 = tg * 16;
                for (int i = tid; i < 16 * DM; i += NTHR) {
                    int tt = i / DM, c = i % DM;
                    float r = __ldcg(&rsrc[(t0 + tt) * DM + c]) + __ldcg(&g_hidden[(t0 + tt) * DM + c]);
                    shn[i] = r;
                    if (og == 0) rdst[(t0 + tt) * DM + c] = r;
                }
                __syncthreads();
                {
                    int tt = tid >> 5, seg = tid & 31;  // 16 tokens x 32 segs of 6
                    float s = 0.f, s2 = 0.f;
#pragma unroll
                    for (int j = 0; j < 6; j++) {
                        float v = shn[tt * DM + seg * 6 + j];
                        s += v; s2 += v * v;
                    }
                    sr1[tt * 32 + seg] = s; sr2[tt * 32 + seg] = s2;
                }
                __syncthreads();
                if (tid < 16) {
                    float s = 0.f, s2 = 0.f;
#pragma unroll
                    for (int j = 0; j < 32; j++) { s += sr1[tid * 32 + j]; s2 += sr2[tid * 32 + j]; }
                    float m = s / DM;
                    stat[tid * 2] = m;
                    stat[tid * 2 + 1] = rsqrtf(s2 / DM - m * m + 1e-5f);
                }
                __syncthreads();
                for (int i = tid; i < 16 * DM; i += NTHR) {
                    int tt = i / DM, c = i % DM;
                    shn[i] = (shn[i] - stat[tt * 2]) * stat[tt * 2 + 1] * ln_w[l * DM + c] + ln_b[l * DM + c];
                }
                __syncthreads();
                int o64 = tid & 63;
                int grp = tid >> 6;  // 8 groups x 2 tokens
                const float* wbase = g_inT + (size_t)(l * DM) * 768 + og * 192 + o64;
                float a0[2] = {}, a1[2] = {}, a2[2] = {};
                for (int k = 0; k < DM; k++) {
                    const float* wk = wbase + (size_t)k * 768;
                    float w0 = wk[0], w1 = wk[64], w2 = wk[128];
#pragma unroll
                    for (int i2 = 0; i2 < 2; i2++) {
                        float xv = shn[(grp * 2 + i2) * DM + k];
                        a0[i2] = fmaf(xv, w0, a0[i2]);
                        a1[i2] = fmaf(xv, w1, a1[i2]);
                        a2[i2] = fmaf(xv, w2, a2[i2]);
                    }
                }
#pragma unroll
                for (int i2 = 0; i2 < 2; i2++) {
                    int t = t0 + grp * 2 + i2;
                    int ob = og * 192 + o64;
                    g_xz[t * 768 + ob] = a0[i2];
                    g_xz[t * 768 + ob + 64] = a1[i2];
                    g_xz[t * 768 + ob + 128] = a2[i2];
                }
                __syncthreads();
            }
        }
        gbar(++ep);

        // ===== phase CONV: conv+silu+xproj+dtproj+rexp (256 vb of dir x 4 scan tokens) =====
        {
            float* sxz  = sm;            // 7*384 = 2688
            float* su   = sm + 2688;     // 1536
            float* sdbl = sm + 4224;     // 176
            for (int vb = bid; vb < 256; vb += GRID) {
                int dir = vb >> 7;
                int q = vb & 127;
                int tq0 = q * 4;
                const float* cw  = dir ? cbw : cfw;
                const float* cb  = dir ? cbb : cfb;
                const float* dtb = dir ? dtbb : dtbf;
                // stage 7 tap rows (scan order)
                for (int i = tid; i < 7 * DI; i += NTHR) {
                    int j = i / DI, d = i % DI;
                    int ts = tq0 - 3 + j;
                    float v = 0.f;
                    if (ts >= 0) {
                        int o = dir ? (511 - ts) : ts;
                        v = __ldcg(&g_xz[o * 768 + d]);
                    }
                    sxz[i] = v;
                }
                __syncthreads();
                // conv + silu; store u (smem+gmem)
                for (int e = tid; e < 4 * DI; e += NTHR) {
                    int t = e / DI, d = e % DI;
                    float4 w4 = *reinterpret_cast<const float4*>(&cw[(l * DI + d) * 4]);
                    float acc = cb[l * DI + d];
                    acc = fmaf(sxz[(t + 0) * DI + d], w4.x, acc);
                    acc = fmaf(sxz[(t + 1) * DI + d], w4.y, acc);
                    acc = fmaf(sxz[(t + 2) * DI + d], w4.z, acc);
                    acc = fmaf(sxz[(t + 3) * DI + d], w4.w, acc);
                    float u = acc / (1.f + __expf(-acc));
                    su[e] = u;
                    int tg = tq0 + t;
                    g_u[dir][tg * DI + d] = u;
                }
                __syncthreads();
                // xproj: 4 tokens x 44 outs, 2 threads per dot (192 each), shfl reduce
                if (tid < 352) {
                    int dot = tid >> 1, hf = tid & 1;
                    int t = dot / XO, o = dot % XO;
                    const float4* xp = reinterpret_cast<const float4*>(
                        g_xpT2 + ((size_t)(l * 2 + dir) * XO + o) * DI + hf * 192);
                    const float4* sur = reinterpret_cast<const float4*>(&su[t * DI + hf * 192]);
                    float b0 = 0.f, b1 = 0.f, b2 = 0.f, b3 = 0.f;
#pragma unroll 4
                    for (int qq = 0; qq < 48; qq++) {
                        float4 uu = sur[qq];
                        float4 ww = xp[qq];
                        b0 = fmaf(uu.x, ww.x, b0);
                        b1 = fmaf(uu.y, ww.y, b1);
                        b2 = fmaf(uu.z, ww.z, b2);
                        b3 = fmaf(uu.w, ww.w, b3);
                    }
                    float acc = (b0 + b1) + (b2 + b3);
                    acc += __shfl_xor_sync(0xffffffffu, acc, 1);
                    if (hf == 0) {
                        sdbl[t * XO + o] = acc;
                        int tg = tq0 + t;
                        if (o >= RK + NS)      g_Cm[dir][tg * NS + (o - RK - NS)] = acc;
                        else if (o >= RK)      g_Bm[dir][tg * NS + (o - RK)] = acc;
                    }
                }
                __syncthreads();
                // dtproj + softplus + rexp
                for (int e = tid; e < 4 * DI; e += NTHR) {
                    int t = e / DI, d = e % DI;
                    float a = dtb[l * DI + d];
                    const float* dw = g_dtT[dir] + (size_t)(l * RK) * DI + d;
#pragma unroll
                    for (int r = 0; r < RK; r++)
                        a = fmaf(sdbl[t * XO + r], dw[(size_t)r * DI], a);
                    float dt = (a > 15.f) ? a : log1pf(__expf(a));
                    int tg = tq0 + t;
                    g_dtv[dir][tg * DI + d] = dt;
                    g_rex[dir][tg * DI + d] = __expf(dt * g_base[dir][l * DI + d]);
                }
                __syncthreads();
            }
        }
        gbar(++ep);

        // ===== phase LOCAL: chunk-local scan -> carries (64 vb of dir x chunk) =====
        {
            float* sB = sm;  // 256
            for (int vb = bid; vb < 64; vb += GRID) {
                int dir = vb >> 5;
                int c = vb & 31;
                if (tid < 256) sB[tid] = __ldcg(&g_Bm[dir][c * CS * NS + tid]);
                __syncthreads();
                if (tid < DI) {
                    int d = tid;
                    float delta[NS], h[NS], pa[NS];
#pragma unroll
                    for (int n = 0; n < NS; n++) {
                        delta[n] = g_delta[dir][(l * NS + n) * DI + d];
                        h[n] = 0.f; pa[n] = 1.f;
                    }
                    for (int t = 0; t < CS; t++) {
                        int tg = c * CS + t;
                        float u  = __ldcg(&g_u[dir][tg * DI + d]);
                        float r  = __ldcg(&g_rex[dir][tg * DI + d]);
                        float dt = __ldcg(&g_dtv[dir][tg * DI + d]);
                        float du = dt * u;
                        float p = 1.f;
#pragma unroll
                        for (int n = 0; n < NS; n++) {
                            p *= r;
                            float dA = p * fmaf(dt, delta[n], 1.f);
                            pa[n] *= dA;
                            h[n] = fmaf(dA, h[n], du * sB[t * NS + n]);
                        }
                    }
#pragma unroll
                    for (int n = 0; n < NS; n++) {
                        g_PA[dir][(c * NS + n) * DI + d] = pa[n];
                        g_HE[dir][(c * NS + n) * DI + d] = h[n];
                    }
                }
                __syncthreads();
            }
        }
        gbar(++ep);

        // ===== phase APPLY+OUT: carries + apply + gate + outproj (64 vb of 8 tokens) =====
        // vb g covers orig tokens [8g, 8g+8): dir0 chunk g>>1, dir1 chunk 31-(g>>1).
        {
            float* sy = sm;          // 8*384 = 3072
            float* sB = sm + 3072;   // 256
            float* sC = sm + 3328;   // 256
            for (int vb = bid; vb < 64; vb += GRID) {
                int g = vb;
                int T0 = g * 8;
                for (int dir = 0; dir < 2; dir++) {
                    int cc = dir ? (31 - (g >> 1)) : (g >> 1);
                    if (tid < 256) {
                        sB[tid] = __ldcg(&g_Bm[dir][cc * CS * NS + tid]);
                        sC[tid] = __ldcg(&g_Cm[dir][cc * CS * NS + tid]);
                    }
                    __syncthreads();
                    if (tid < DI) {
                        int d = tid;
                        float delta[NS], h[NS];
#pragma unroll
                        for (int n = 0; n < NS; n++) {
                            delta[n] = g_delta[dir][(l * NS + n) * DI + d];
                            h[n] = 0.f;
                        }
                        float Dv = g_Dva[dir][l * DI + d];
                        for (int cp = 0; cp < cc; cp++) {
#pragma unroll
                            for (int n = 0; n < NS; n++)
                                h[n] = fmaf(__ldcg(&g_PA[dir][(cp * NS + n) * DI + d]), h[n],
                                            __ldcg(&g_HE[dir][(cp * NS + n) * DI + d]));
                        }
                        for (int i = 0; i < CS; i++) {
                            int tg = cc * CS + i;
                            float u  = __ldcg(&g_u[dir][tg * DI + d]);
                            float r  = __ldcg(&g_rex[dir][tg * DI + d]);
                            float dt = __ldcg(&g_dtv[dir][tg * DI + d]);
                            float du = dt * u;
                            float p = 1.f, y = 0.f;
#pragma unroll
                            for (int n = 0; n < NS; n++) {
                                p *= r;
                                float dA = p * fmaf(dt, delta[n], 1.f);
                                h[n] = fmaf(dA, h[n], du * sB[i * NS + n]);
                                y = fmaf(h[n], sC[i * NS + n], y);
                            }
                            int local = dir ? (511 - tg - T0) : (tg - T0);
                            if ((unsigned)local < 8u) {
                                // z read straight from xz (original token order)
                                float z = __ldcg(&g_xz[(T0 + local) * 768 + DI + d]);
                                y = fmaf(u, Dv, y);
                                float sg = z / (1.f + __expf(-z));
                                float val = y * sg;
                                if (dir == 0) sy[local * DI + d] = val;
                                else          sy[local * DI + d] += val;
                            }
                        }
                    }
                    __syncthreads();
                }
                // outproj: 8 tokens x 192 outs from smem y
                if (tid < 384) {
                    int o = tid % DM;
                    int th = tid / DM;  // 0..1, 4 tokens each
                    const float* wb = g_outT + (size_t)l * DI * DM + o;
                    float acc[4] = {};
                    for (int k = 0; k < DI; k++) {
                        float w = wb[(size_t)k * DM];
#pragma unroll
                        for (int tt = 0; tt < 4; tt++)
                            acc[tt] = fmaf(sy[(th * 4 + tt) * DI + k], w, acc[tt]);
                    }
#pragma unroll
                    for (int tt = 0; tt < 4; tt++)
                        g_hidden[(T0 + th * 4 + tt) * DM + o] = acc[tt];
                }
                __syncthreads();
            }
        }
        gbar(++ep);
    }

    // ===== final: LN(resid + hidden)[511] @ head (block 0) =====
    if (bid == 0) {
        float* sv   = sm;        // 192
        float* red1 = sm + 192;  // 32
        float* red2 = sm + 224;  // 32
        float* st   = sm + 256;  // 2
        if (tid < DM)
            sv[tid] = __ldcg(&g_resid[0][511 * DM + tid]) + __ldcg(&g_hidden[511 * DM + tid]);
        __syncthreads();
        if (tid < 32) {
            float s = 0.f, s2 = 0.f;
#pragma unroll
            for (int j = 0; j < 6; j++) {
                float x = sv[tid * 6 + j];
                s += x; s2 += x * x;
            }
            red1[tid] = s; red2[tid] = s2;
        }
        __syncthreads();
        if (tid == 0) {
            float s = 0.f, s2 = 0.f;
#pragma unroll
            for (int j = 0; j < 32; j++) { s += red1[j]; s2 += red2[j]; }
            float m = s / DM;
            st[0] = m;
            st[1] = rsqrtf(s2 / DM - m * m + 1e-5f);
        }
        __syncthreads();
        if (tid < DM) sv[tid] = (sv[tid] - st[0]) * st[1] * nfw[tid] + nfb[tid];
        __syncthreads();
        if (tid < 2) {
            float a = hb[tid];
            for (int c = 0; c < DM; c++) a = fmaf(sv[c], hw[tid * DM + c], a);
            out[tid] = a;
        }
    }
}

extern "C" void kernel_launch(void* const* d_in, const int* in_sizes, int n_in,
                              void* d_out, int out_size) {
    const float* x       = (const float*)d_in[0];
    const float* patch_w = (const float*)d_in[1];
    const float* patch_b = (const float*)d_in[2];
    const float* ln_w    = (const float*)d_in[3];
    const float* ln_b    = (const float*)d_in[4];
    const float* in_w    = (const float*)d_in[5];
    const float* cf_w    = (const float*)d_in[6];
    const float* cf_b    = (const float*)d_in[7];
    const float* xpf_w   = (const float*)d_in[8];
    const float* dtf_w   = (const float*)d_in[9];
    const float* dtf_b   = (const float*)d_in[10];
    const float* Alog_f  = (const float*)d_in[11];
    const float* D_f     = (const float*)d_in[12];
    const float* cbk_w   = (const float*)d_in[13];
    const float* cbk_b   = (const float*)d_in[14];
    const float* xpb_w   = (const float*)d_in[15];
    const float* dtb_w   = (const float*)d_in[16];
    const float* dtb_b   = (const float*)d_in[17];
    const float* Alog_b  = (const float*)d_in[18];
    const float* D_b     = (const float*)d_in[19];
    const float* out_w   = (const float*)d_in[20];
    const float* nf_w    = (const float*)d_in[21];
    const float* nf_b    = (const float*)d_in[22];
    const float* head_w  = (const float*)d_in[23];
    const float* head_b  = (const float*)d_in[24];
    float* out = (float*)d_out;

    k_setup_w<<<5184, 256>>>(in_w, out_w);                                   // launch 0
    k_setup_misc<<<256, 256>>>(xpf_w, xpb_w, dtf_w, dtb_w,
                               Alog_f, Alog_b, D_f, D_b);                    // launch 1
    k_patch_gemm<<<dim3(8, 3, 8), 256>>>(x, patch_w);                        // launch 2
    k_mamba<<<GRID, NTHR>>>(ln_w, ln_b, cf_w, cf_b, cbk_w, cbk_b,
                            dtf_b, dtb_b, nf_w, nf_b,
                            head_w, head_b, patch_b, out);                   // launch 3
}

// round 17
// speedup vs baseline: 2.0118x; 1.0936x over previous
#include <cuda_runtime.h>
#include <cuda_bf16.h>
#include <math.h>

#define LSEQ 512
#define DM   192
#define DI   384
#define NS   16
#define RK   12
#define XO   44      // RK + 2*NS
#define NLAY 24
#define NCH  32
#define CS   16      // LSEQ / NCH
#define GRID 148
#define NTHR 512

// ---------------- scratch (static device globals; no runtime allocation) ----------------
__device__ float g_hidden[LSEQ * DM];
__device__ float g_resid[2][LSEQ * DM];          // ping-pong
__device__ float g_xz[LSEQ * 2 * DI];
__device__ float g_u[2][LSEQ * DI];
__device__ float g_dtv[2][LSEQ * DI];
__device__ float g_rex[2][LSEQ * DI];
__device__ float g_Bm[2][LSEQ * NS];
__device__ float g_Cm[2][LSEQ * NS];
__device__ float g_PA[2][NCH * NS * DI];
__device__ float g_HE[2][NCH * NS * DI];
__device__ float g_H0[2][NCH * NS * DI];         // prefix state entering each chunk
// patch-embed scratch
__device__ float g_ppart[8 * LSEQ * DM];
// preprocessed weights
__device__ float g_inT[NLAY * DM * 2 * DI];      // [l][k][o]
__device__ float g_outT[NLAY * DI * DM];         // [l][d][c]
__device__ float g_xpT2[NLAY * 2 * XO * DI];     // [l][dir][o][d]
__device__ float g_dtT[2][NLAY * RK * DI];       // [l][r][d]
__device__ float g_base[2][NLAY * DI];           // A0 = -exp(Alog[...,0])
__device__ float g_delta[2][NLAY * NS * DI];     // An - (n+1)*A0, [l][n][d]
__device__ float g_Dva[2][NLAY * DI];
// software grid barrier state (separate cache lines; reset each replay)
__device__ unsigned g_cnt[32];
__device__ volatile unsigned g_epoch[32];

// ---------------- software grid barrier (grid must be exactly GRID blocks) ----------------
__device__ __forceinline__ void gbar(unsigned e) {
    __syncthreads();
    if (threadIdx.x == 0) {
        __threadfence();
        unsigned prev = atomicAdd(&g_cnt[0], 1u);
        if (prev == e * GRID - 1u) {
            g_epoch[0] = e;
            __threadfence();
        } else {
            while (g_epoch[0] < e) __nanosleep(64);
        }
    }
    __syncthreads();
}

// ---------------- launch 0: coalesced tiled transposes of in_w / out_w ----------------
__global__ void k_setup_w(const float* __restrict__ in_w, const float* __restrict__ out_w) {
    __shared__ float tile[32][33];
    int b = blockIdx.x;
    int tx = threadIdx.x & 31, ty = threadIdx.x >> 5;  // 8 rows per pass
    if (b < 3456) {
        // in_w (24, 768, 192) -> g_inT [l][k][o]
        int l = b / 144; int r = b % 144; int ot = r / 6; int kt = r % 6;
        const float* src = in_w + (size_t)l * 768 * 192;
        float* dst = g_inT + (size_t)l * 192 * 768;
        int o0 = ot * 32, k0 = kt * 32;
        for (int rr = ty; rr < 32; rr += 8)
            tile[rr][tx] = src[(size_t)(o0 + rr) * 192 + k0 + tx];
        __syncthreads();
        for (int rr = ty; rr < 32; rr += 8)
            dst[(size_t)(k0 + rr) * 768 + o0 + tx] = tile[tx][rr];
    } else {
        // out_w (24, 192, 384) -> g_outT [l][d][c]
        b -= 3456;
        int l = b / 72; int r = b % 72; int ct = r / 12; int dt = r % 12;
        const float* src = out_w + (size_t)l * 192 * 384;
        float* dst = g_outT + (size_t)l * 384 * 192;
        int c0 = ct * 32, d0 = dt * 32;
        for (int rr = ty; rr < 32; rr += 8)
            tile[rr][tx] = src[(size_t)(c0 + rr) * 384 + d0 + tx];
        __syncthreads();
        for (int rr = ty; rr < 32; rr += 8)
            dst[(size_t)(d0 + rr) * 192 + c0 + tx] = tile[tx][rr];
    }
}

// ---------------- launch 1: small copies + A-derived + zero resid + barrier reset ----------------
__global__ void k_setup_misc(const float* __restrict__ xpf, const float* __restrict__ xpb,
                             const float* __restrict__ dtfw, const float* __restrict__ dtbw,
                             const float* __restrict__ Alog_f, const float* __restrict__ Alog_b,
                             const float* __restrict__ D_f, const float* __restrict__ D_b) {
    int tid = blockIdx.x * blockDim.x + threadIdx.x;
    int nth = gridDim.x * blockDim.x;
    if (tid == 0) { g_cnt[0] = 0; g_epoch[0] = 0; }
    // xp (24,44,384) is already [l][o][d] -> interleave dirs
    for (int i = tid; i < NLAY * XO * DI; i += nth) {
        int l = i / (XO * DI); int r = i % (XO * DI);
        g_xpT2[(size_t)(l * 2 + 0) * XO * DI + r] = xpf[i];
        g_xpT2[(size_t)(l * 2 + 1) * XO * DI + r] = xpb[i];
    }
    // dt_w (24,384,12) -> [l][r][d]
    for (int i = tid; i < NLAY * DI * RK; i += nth) {
        int l = i / (DI * RK); int r2 = i % (DI * RK); int d = r2 / RK; int rr = r2 % RK;
        g_dtT[0][(l * RK + rr) * DI + d] = dtfw[i];
        g_dtT[1][(l * RK + rr) * DI + d] = dtbw[i];
    }
    // A-derived per (l,d)
    for (int i = tid; i < NLAY * DI; i += nth) {
        int l = i / DI; int d = i % DI;
        for (int dir = 0; dir < 2; dir++) {
            const float* Alog = dir ? Alog_b : Alog_f;
            float A0 = -expf(Alog[i * NS + 0]);
            g_base[dir][i] = A0;
            for (int n = 0; n < NS; n++) {
                float An = -expf(Alog[i * NS + n]);
                g_delta[dir][(l * NS + n) * DI + d] = An - (float)(n + 1) * A0;
            }
        }
        g_Dva[0][i] = D_f[i];
        g_Dva[1][i] = D_b[i];
    }
    for (int i = tid; i < LSEQ * DM; i += nth) g_resid[0][i] = 0.f;
}

// ---------------- launch 2: patch embed split-K GEMM with inline gather ----------------
__global__ void k_patch_gemm(const float* __restrict__ x, const float* __restrict__ pw) {
    __shared__ float sA[64][65];
    __shared__ float sB[64][65];
    int p0 = blockIdx.x * 64;
    int c0 = blockIdx.y * 64;
    int ks = blockIdx.z;
    int tid = threadIdx.x;
    int tr = tid >> 4, tc = tid & 15;
    float acc[4][4] = {};
    for (int kt = 0; kt < 8; kt++) {
        int kb = ks * 512 + kt * 64;
        int kk = tid & 63;
        int r0 = tid >> 6;
        for (int r = r0; r < 64; r += 4) {
            int p = p0 + r;
            int k = kb + kk;
            int pz = p >> 6, py = (p >> 3) & 7, px = p & 7;
            int dz = k >> 8, dy = (k >> 4) & 15, dx = k & 15;
            sA[r][kk] = x[((pz * 16 + dz) * 128 + (py * 16 + dy)) * 128 + (px * 16 + dx)];
            sB[kk][r] = pw[(size_t)(c0 + r) * 4096 + kb + kk];
        }
        __syncthreads();
        for (int q = 0; q < 64; q++) {
            float a[4], b[4];
#pragma unroll
            for (int i = 0; i < 4; i++) a[i] = sA[tr * 4 + i][q];
#pragma unroll
            for (int j = 0; j < 4; j++) b[j] = sB[q][tc * 4 + j];
#pragma unroll
            for (int i = 0; i < 4; i++)
#pragma unroll
                for (int j = 0; j < 4; j++)
                    acc[i][j] = fmaf(a[i], b[j], acc[i][j]);
        }
        __syncthreads();
    }
#pragma unroll
    for (int i = 0; i < 4; i++)
#pragma unroll
        for (int j = 0; j < 4; j++)
            g_ppart[((size_t)ks * LSEQ + p0 + tr * 4 + i) * DM + c0 + tc * 4 + j] = acc[i][j];
}

// ---------------- launch 3: THE persistent kernel ----------------
// grid exactly 148 x 512 threads. Cross-block activation reads use __ldcg (L2-only);
// weights written in earlier launches are safe to cache in L1.
__global__ void __launch_bounds__(NTHR) k_mamba(
    const float* __restrict__ ln_w, const float* __restrict__ ln_b,
    const float* __restrict__ cfw, const float* __restrict__ cfb,
    const float* __restrict__ cbw, const float* __restrict__ cbb,
    const float* __restrict__ dtbf, const float* __restrict__ dtbb,
    const float* __restrict__ nfw, const float* __restrict__ nfb,
    const float* __restrict__ hw, const float* __restrict__ hb,
    const float* __restrict__ pb, float* __restrict__ out)
{
    __shared__ float sm[4416];
    const int bid = blockIdx.x;
    const int tid = threadIdx.x;
    unsigned ep = 0;

    // ---- patch reduce (+bias) -> g_hidden ----
    for (int i = bid * NTHR + tid; i < LSEQ * DM; i += GRID * NTHR) {
        int c = i % DM;
        float s = pb[c];
#pragma unroll
        for (int ks = 0; ks < 8; ks++) s += g_ppart[(size_t)ks * LSEQ * DM + i];
        g_hidden[i] = s;
    }
    gbar(++ep);

    for (int l = 0; l < NLAY; l++) {
        // ===== phase IN: residual + LN + inproj GEMM (128 vb of 16 tok x 192 out) =====
        {
            float* shn  = sm;            // 3072
            float* sr1  = sm + 3072;     // 512
            float* sr2  = sm + 3584;     // 512
            float* stat = sm + 4096;     // 32
            int rb = l & 1;
            const float* rsrc = g_resid[rb];
            float* rdst = g_resid[rb ^ 1];
            for (int vb = bid; vb < 128; vb += GRID) {
                int tg = vb & 31, og = vb >> 5;
                int t0 = tg * 16;
                for (int i = tid; i < 16 * DM; i += NTHR) {
                    int tt = i / DM, c = i % DM;
                    float r = __ldcg(&rsrc[(t0 + tt) * DM + c]) + __ldcg(&g_hidden[(t0 + tt) * DM + c]);
                    shn[i] = r;
                    if (og == 0) rdst[(t0 + tt) * DM + c] = r;
                }
                __syncthreads();
                {
                    int tt = tid >> 5, seg = tid & 31;  // 16 tokens x 32 segs of 6
                    float s = 0.f, s2 = 0.f;
#pragma unroll
                    for (int j = 0; j < 6; j++) {
                        float v = shn[tt * DM + seg * 6 + j];
                        s += v; s2 += v * v;
                    }
                    sr1[tt * 32 + seg] = s; sr2[tt * 32 + seg] = s2;
                }
                __syncthreads();
                if (tid < 16) {
                    float s = 0.f, s2 = 0.f;
#pragma unroll
                    for (int j = 0; j < 32; j++) { s += sr1[tid * 32 + j]; s2 += sr2[tid * 32 + j]; }
                    float m = s / DM;
                    stat[tid * 2] = m;
                    stat[tid * 2 + 1] = rsqrtf(s2 / DM - m * m + 1e-5f);
                }
                __syncthreads();
                for (int i = tid; i < 16 * DM; i += NTHR) {
                    int tt = i / DM, c = i % DM;
                    shn[i] = (shn[i] - stat[tt * 2]) * stat[tt * 2 + 1] * ln_w[l * DM + c] + ln_b[l * DM + c];
                }
                __syncthreads();
                int o64 = tid & 63;
                int grp = tid >> 6;  // 8 groups x 2 tokens
                const float* wbase = g_inT + (size_t)(l * DM) * 768 + og * 192 + o64;
                float a0[2] = {}, a1[2] = {}, a2[2] = {};
                for (int k = 0; k < DM; k++) {
                    const float* wk = wbase + (size_t)k * 768;
                    float w0 = wk[0], w1 = wk[64], w2 = wk[128];
#pragma unroll
                    for (int i2 = 0; i2 < 2; i2++) {
                        float xv = shn[(grp * 2 + i2) * DM + k];
                        a0[i2] = fmaf(xv, w0, a0[i2]);
                        a1[i2] = fmaf(xv, w1, a1[i2]);
                        a2[i2] = fmaf(xv, w2, a2[i2]);
                    }
                }
#pragma unroll
                for (int i2 = 0; i2 < 2; i2++) {
                    int t = t0 + grp * 2 + i2;
                    int ob = og * 192 + o64;
                    g_xz[t * 768 + ob] = a0[i2];
                    g_xz[t * 768 + ob + 64] = a1[i2];
                    g_xz[t * 768 + ob + 128] = a2[i2];
                }
                __syncthreads();
            }
        }
        gbar(++ep);

        // ===== phase CONV: conv+silu+xproj+dtproj+rexp (256 vb of dir x 4 scan tokens) =====
        {
            float* sxz  = sm;            // 7*384 = 2688
            float* su   = sm + 2688;     // 1536
            float* sdbl = sm + 4224;     // 176
            for (int vb = bid; vb < 256; vb += GRID) {
                int dir = vb >> 7;
                int q = vb & 127;
                int tq0 = q * 4;
                const float* cw  = dir ? cbw : cfw;
                const float* cb  = dir ? cbb : cfb;
                const float* dtb = dir ? dtbb : dtbf;
                // stage 7 tap rows (scan order)
                for (int i = tid; i < 7 * DI; i += NTHR) {
                    int j = i / DI, d = i % DI;
                    int ts = tq0 - 3 + j;
                    float v = 0.f;
                    if (ts >= 0) {
                        int o = dir ? (511 - ts) : ts;
                        v = __ldcg(&g_xz[o * 768 + d]);
                    }
                    sxz[i] = v;
                }
                __syncthreads();
                // conv + silu; store u (smem+gmem)
                for (int e = tid; e < 4 * DI; e += NTHR) {
                    int t = e / DI, d = e % DI;
                    float4 w4 = *reinterpret_cast<const float4*>(&cw[(l * DI + d) * 4]);
                    float acc = cb[l * DI + d];
                    acc = fmaf(sxz[(t + 0) * DI + d], w4.x, acc);
                    acc = fmaf(sxz[(t + 1) * DI + d], w4.y, acc);
                    acc = fmaf(sxz[(t + 2) * DI + d], w4.z, acc);
                    acc = fmaf(sxz[(t + 3) * DI + d], w4.w, acc);
                    float u = acc / (1.f + __expf(-acc));
                    su[e] = u;
                    int tg = tq0 + t;
                    g_u[dir][tg * DI + d] = u;
                }
                __syncthreads();
                // xproj: 4 tokens x 44 outs, 2 threads per dot (192 each), shfl reduce
                if (tid < 352) {
                    int dot = tid >> 1, hf = tid & 1;
                    int t = dot / XO, o = dot % XO;
                    const float4* xp = reinterpret_cast<const float4*>(
                        g_xpT2 + ((size_t)(l * 2 + dir) * XO + o) * DI + hf * 192);
                    const float4* sur = reinterpret_cast<const float4*>(&su[t * DI + hf * 192]);
                    float b0 = 0.f, b1 = 0.f, b2 = 0.f, b3 = 0.f;
#pragma unroll 4
                    for (int qq = 0; qq < 48; qq++) {
                        float4 uu = sur[qq];
                        float4 ww = xp[qq];
                        b0 = fmaf(uu.x, ww.x, b0);
                        b1 = fmaf(uu.y, ww.y, b1);
                        b2 = fmaf(uu.z, ww.z, b2);
                        b3 = fmaf(uu.w, ww.w, b3);
                    }
                    float acc = (b0 + b1) + (b2 + b3);
                    acc += __shfl_xor_sync(0xffffffffu, acc, 1);
                    if (hf == 0) {
                        sdbl[t * XO + o] = acc;
                        int tg = tq0 + t;
                        if (o >= RK + NS)      g_Cm[dir][tg * NS + (o - RK - NS)] = acc;
                        else if (o >= RK)      g_Bm[dir][tg * NS + (o - RK)] = acc;
                    }
                }
                __syncthreads();
                // dtproj + softplus + rexp
                for (int e = tid; e < 4 * DI; e += NTHR) {
                    int t = e / DI, d = e % DI;
                    float a = dtb[l * DI + d];
                    const float* dw = g_dtT[dir] + (size_t)(l * RK) * DI + d;
#pragma unroll
                    for (int r = 0; r < RK; r++)
                        a = fmaf(sdbl[t * XO + r], dw[(size_t)r * DI], a);
                    float dt = (a > 15.f) ? a : log1pf(__expf(a));
                    int tg = tq0 + t;
                    g_dtv[dir][tg * DI + d] = dt;
                    g_rex[dir][tg * DI + d] = __expf(dt * g_base[dir][l * DI + d]);
                }
                __syncthreads();
            }
        }
        gbar(++ep);

        // ===== phase LOCAL: chunk-local scan -> carries (64 vb of dir x chunk) =====
        {
            float* sB = sm;  // 256
            for (int vb = bid; vb < 64; vb += GRID) {
                int dir = vb >> 5;
                int c = vb & 31;
                if (tid < 256) sB[tid] = __ldcg(&g_Bm[dir][c * CS * NS + tid]);
                __syncthreads();
                if (tid < DI) {
                    int d = tid;
                    float delta[NS], h[NS], pa[NS];
#pragma unroll
                    for (int n = 0; n < NS; n++) {
                        delta[n] = g_delta[dir][(l * NS + n) * DI + d];
                        h[n] = 0.f; pa[n] = 1.f;
                    }
                    for (int t = 0; t < CS; t++) {
                        int tg = c * CS + t;
                        float u  = __ldcg(&g_u[dir][tg * DI + d]);
                        float r  = __ldcg(&g_rex[dir][tg * DI + d]);
                        float dt = __ldcg(&g_dtv[dir][tg * DI + d]);
                        float du = dt * u;
                        float p = 1.f;
#pragma unroll
                        for (int n = 0; n < NS; n++) {
                            p *= r;
                            float dA = p * fmaf(dt, delta[n], 1.f);
                            pa[n] *= dA;
                            h[n] = fmaf(dA, h[n], du * sB[t * NS + n]);
                        }
                    }
#pragma unroll
                    for (int n = 0; n < NS; n++) {
                        g_PA[dir][(c * NS + n) * DI + d] = pa[n];
                        g_HE[dir][(c * NS + n) * DI + d] = h[n];
                    }
                }
                __syncthreads();
            }
        }
        gbar(++ep);

        // ===== phase SCAN2: cross-chunk prefix of carries -> H0 (24 blocks active) =====
        // 12288 independent scans (dir, n*DI+d), d fastest for coalescing.
        {
            int gt = bid * NTHR + tid;
            if (gt < 2 * NS * DI) {
                int dir = gt / (NS * DI);
                int nd = gt % (NS * DI);
                float h = 0.f;
#pragma unroll 4
                for (int c = 0; c < NCH; c++) {
                    size_t idx = (size_t)c * NS * DI + nd;
                    float pa = __ldcg(&g_PA[dir][idx]);
                    float he = __ldcg(&g_HE[dir][idx]);
                    g_H0[dir][idx] = h;
                    h = fmaf(pa, h, he);
                }
            }
        }
        gbar(++ep);

        // ===== phase APPLY+OUT: H0-init + apply + gate + outproj (64 vb of 8 tokens) =====
        // vb g covers orig tokens [8g, 8g+8): dir0 chunk g>>1, dir1 chunk 31-(g>>1).
        {
            float* sy = sm;          // 8*384 = 3072
            float* sB = sm + 3072;   // 256
            float* sC = sm + 3328;   // 256
            for (int vb = bid; vb < 64; vb += GRID) {
                int g = vb;
                int T0 = g * 8;
                for (int dir = 0; dir < 2; dir++) {
                    int cc = dir ? (31 - (g >> 1)) : (g >> 1);
                    if (tid < 256) {
                        sB[tid] = __ldcg(&g_Bm[dir][cc * CS * NS + tid]);
                        sC[tid] = __ldcg(&g_Cm[dir][cc * CS * NS + tid]);
                    }
                    __syncthreads();
                    if (tid < DI) {
                        int d = tid;
                        float delta[NS], h[NS];
#pragma unroll
                        for (int n = 0; n < NS; n++) {
                            delta[n] = g_delta[dir][(l * NS + n) * DI + d];
                            h[n] = __ldcg(&g_H0[dir][(cc * NS + n) * DI + d]);
                        }
                        float Dv = g_Dva[dir][l * DI + d];
                        for (int i = 0; i < CS; i++) {
                            int tg = cc * CS + i;
                            float u  = __ldcg(&g_u[dir][tg * DI + d]);
                            float r  = __ldcg(&g_rex[dir][tg * DI + d]);
                            float dt = __ldcg(&g_dtv[dir][tg * DI + d]);
                            float du = dt * u;
                            float p = 1.f, y = 0.f;
#pragma unroll
                            for (int n = 0; n < NS; n++) {
                                p *= r;
                                float dA = p * fmaf(dt, delta[n], 1.f);
                                h[n] = fmaf(dA, h[n], du * sB[i * NS + n]);
                                y = fmaf(h[n], sC[i * NS + n], y);
                            }
                            int local = dir ? (511 - tg - T0) : (tg - T0);
                            if ((unsigned)local < 8u) {
                                // z read straight from xz (original token order)
                                float z = __ldcg(&g_xz[(T0 + local) * 768 + DI + d]);
                                y = fmaf(u, Dv, y);
                                float sg = z / (1.f + __expf(-z));
                                float val = y * sg;
                                if (dir == 0) sy[local * DI + d] = val;
                                else          sy[local * DI + d] += val;
                            }
                        }
                    }
                    __syncthreads();
                }
                // outproj: 8 tokens x 192 outs from smem y
                if (tid < 384) {
                    int o = tid % DM;
                    int th = tid / DM;  // 0..1, 4 tokens each
                    const float* wb = g_outT + (size_t)l * DI * DM + o;
                    float acc[4] = {};
                    for (int k = 0; k < DI; k++) {
                        float w = wb[(size_t)k * DM];
#pragma unroll
                        for (int tt = 0; tt < 4; tt++)
                            acc[tt] = fmaf(sy[(th * 4 + tt) * DI + k], w, acc[tt]);
                    }
#pragma unroll
                    for (int tt = 0; tt < 4; tt++)
                        g_hidden[(T0 + th * 4 + tt) * DM + o] = acc[tt];
                }
                __syncthreads();
            }
        }
        gbar(++ep);
    }

    // ===== final: LN(resid + hidden)[511] @ head (block 0) =====
    if (bid == 0) {
        float* sv   = sm;        // 192
        float* red1 = sm + 192;  // 32
        float* red2 = sm + 224;  // 32
        float* st   = sm + 256;  // 2
        if (tid < DM)
            sv[tid] = __ldcg(&g_resid[0][511 * DM + tid]) + __ldcg(&g_hidden[511 * DM + tid]);
        __syncthreads();
        if (tid < 32) {
            float s = 0.f, s2 = 0.f;
#pragma unroll
            for (int j = 0; j < 6; j++) {
                float x = sv[tid * 6 + j];
                s += x; s2 += x * x;
            }
            red1[tid] = s; red2[tid] = s2;
        }
        __syncthreads();
        if (tid == 0) {
            float s = 0.f, s2 = 0.f;
#pragma unroll
            for (int j = 0; j < 32; j++) { s += red1[j]; s2 += red2[j]; }
            float m = s / DM;
            st[0] = m;
            st[1] = rsqrtf(s2 / DM - m * m + 1e-5f);
        }
        __syncthreads();
        if (tid < DM) sv[tid] = (sv[tid] - st[0]) * st[1] * nfw[tid] + nfb[tid];
        __syncthreads();
        if (tid < 2) {
            float a = hb[tid];
            for (int c = 0; c < DM; c++) a = fmaf(sv[c], hw[tid * DM + c], a);
            out[tid] = a;
        }
    }
}

extern "C" void kernel_launch(void* const* d_in, const int* in_sizes, int n_in,
                              void* d_out, int out_size) {
    const float* x       = (const float*)d_in[0];
    const float* patch_w = (const float*)d_in[1];
    const float* patch_b = (const float*)d_in[2];
    const float* ln_w    = (const float*)d_in[3];
    const float* ln_b    = (const float*)d_in[4];
    const float* in_w    = (const float*)d_in[5];
    const float* cf_w    = (const float*)d_in[6];
    const float* cf_b    = (const float*)d_in[7];
    const float* xpf_w   = (const float*)d_in[8];
    const float* dtf_w   = (const float*)d_in[9];
    const float* dtf_b   = (const float*)d_in[10];
    const float* Alog_f  = (const float*)d_in[11];
    const float* D_f     = (const float*)d_in[12];
    const float* cbk_w   = (const float*)d_in[13];
    const float* cbk_b   = (const float*)d_in[14];
    const float* xpb_w   = (const float*)d_in[15];
    const float* dtb_w   = (const float*)d_in[16];
    const float* dtb_b   = (const float*)d_in[17];
    const float* Alog_b  = (const float*)d_in[18];
    const float* D_b     = (const float*)d_in[19];
    const float* out_w   = (const float*)d_in[20];
    const float* nf_w    = (const float*)d_in[21];
    const float* nf_b    = (const float*)d_in[22];
    const float* head_w  = (const float*)d_in[23];
    const float* head_b  = (const float*)d_in[24];
    float* out = (float*)d_out;

    k_setup_w<<<5184, 256>>>(in_w, out_w);                                   // launch 0
    k_setup_misc<<<256, 256>>>(xpf_w, xpb_w, dtf_w, dtb_w,
                               Alog_f, Alog_b, D_f, D_b);                    // launch 1
    k_patch_gemm<<<dim3(8, 3, 8), 256>>>(x, patch_w);                        // launch 2
    k_mamba<<<GRID, NTHR>>>(ln_w, ln_b, cf_w, cf_b, cbk_w, cbk_b,
                            dtf_b, dtb_b, nf_w, nf_b,
                            head_w, head_b, patch_b, out);                   // launch 3
}